// round 2
// baseline (speedup 1.0000x reference)
#include <cuda_runtime.h>
#include <cstdint>

#define B 8
#define C 256
#define N 4096            // 64*64
#define G 8
#define CG 32             // channels per group
#define EPS 1e-5f
#define SCALE 0.0625f     // 1/sqrt(256)

// ---------------- scratch (static device allocations are allowed) -------------
__device__ float g_xn[(size_t)B * C * N];      // groupnormed x, [b][c][n]
__device__ float g_q[(size_t)B * N * C];       // Q [b][n][c]
__device__ float g_k[(size_t)B * N * C];       // K [b][n][c]
__device__ float g_v[(size_t)B * N * C];       // V [b][n][c]
__device__ float g_att[(size_t)B * N * C];     // attention out [b][n][c]
__device__ float g_mean[B * G];
__device__ float g_rstd[B * G];

// ---------------- kernel 1: groupnorm stats ----------------------------------
__global__ void gn_stats(const float* __restrict__ x) {
    int bg = blockIdx.x;                         // 0..63, contiguous 32*4096 chunk
    const float4* p = (const float4*)(x + (size_t)bg * CG * N);
    float s = 0.f, ss = 0.f;
    for (int i = threadIdx.x; i < (CG * N) / 4; i += blockDim.x) {
        float4 v = p[i];
        s  += v.x + v.y + v.z + v.w;
        ss += v.x * v.x + v.y * v.y + v.z * v.z + v.w * v.w;
    }
    for (int o = 16; o > 0; o >>= 1) {
        s  += __shfl_down_sync(0xffffffffu, s, o);
        ss += __shfl_down_sync(0xffffffffu, ss, o);
    }
    __shared__ float rs[8], rss[8];
    int wid = threadIdx.x >> 5, lid = threadIdx.x & 31;
    if (lid == 0) { rs[wid] = s; rss[wid] = ss; }
    __syncthreads();
    if (threadIdx.x == 0) {
        float ts = 0.f, tss = 0.f;
        for (int i = 0; i < 8; i++) { ts += rs[i]; tss += rss[i]; }
        float inv = 1.0f / (float)(CG * N);
        float mean = ts * inv;
        float var = tss * inv - mean * mean;
        g_mean[bg] = mean;
        g_rstd[bg] = rsqrtf(var + EPS);
    }
}

// ---------------- kernel 2: groupnorm apply ----------------------------------
__global__ void gn_apply(const float* __restrict__ x,
                         const float* __restrict__ sc,
                         const float* __restrict__ bi) {
    int i = blockIdx.x * blockDim.x + threadIdx.x;      // float4 index
    int e = i << 2;                                     // element index
    int c = (e >> 12) & (C - 1);                        // /4096 % 256
    int bg = e >> 17;                                   // /131072
    float m = g_mean[bg], r = g_rstd[bg];
    float a = sc[c] * r;
    float b = bi[c] - m * a;
    float4 v = ((const float4*)x)[i];
    float4 o;
    o.x = v.x * a + b; o.y = v.y * a + b; o.z = v.z * a + b; o.w = v.w * a + b;
    ((float4*)g_xn)[i] = o;
}

// ---------------- kernel 3: QKV GEMM (768 x 4096 x 256 per batch) ------------
// out: q/k/v transposed to [b][n][c]
__global__ void qkv_gemm(const float* __restrict__ W, const float* __restrict__ bias) {
    int b = blockIdx.z;
    int o0 = blockIdx.y * 64;
    int n0 = blockIdx.x * 64;
    __shared__ float As[64][33];    // [o][k]
    __shared__ float Bs[32][65];    // [k][n]
    const float* Xb = g_xn + (size_t)b * C * N;
    float acc[4][4] = {};
    int tx = threadIdx.x & 15, ty = threadIdx.x >> 4;
    for (int k0 = 0; k0 < C; k0 += 32) {
        for (int i = threadIdx.x; i < 64 * 32; i += 256) {
            int rr = i >> 5, cc = i & 31;
            As[rr][cc] = W[(size_t)(o0 + rr) * C + k0 + cc];
        }
        for (int i = threadIdx.x; i < 32 * 64; i += 256) {
            int kk = i >> 6, nn = i & 63;
            Bs[kk][nn] = Xb[(size_t)(k0 + kk) * N + n0 + nn];
        }
        __syncthreads();
#pragma unroll
        for (int k = 0; k < 32; k++) {
            float a[4], bb[4];
#pragma unroll
            for (int i = 0; i < 4; i++) a[i] = As[ty * 4 + i][k];
#pragma unroll
            for (int j = 0; j < 4; j++) bb[j] = Bs[k][tx * 4 + j];
#pragma unroll
            for (int i = 0; i < 4; i++)
#pragma unroll
                for (int j = 0; j < 4; j++) acc[i][j] += a[i] * bb[j];
        }
        __syncthreads();
    }
#pragma unroll
    for (int i = 0; i < 4; i++) {
        int o = o0 + ty * 4 + i;
        float bv = bias[o];
        float* dst; int oc;
        if (o < 256)      { dst = g_q; oc = o; }
        else if (o < 512) { dst = g_k; oc = o - 256; }
        else              { dst = g_v; oc = o - 512; }
#pragma unroll
        for (int j = 0; j < 4; j++) {
            int n = n0 + tx * 4 + j;
            dst[((size_t)b * N + n) * C + oc] = acc[i][j] + bv;
        }
    }
}

// ---------------- kernel 4: flash attention (fp32, <=48KB static smem) --------
// Br = Bc = 64, 256 threads. Q/K/V in [b][n][c].
// Smem plan:
//   stage[4224]   : Q(64x33)+K(64x33) during S phase, reused as V chunk (16x257)
//   Ps[64*65]     : S tile / P tile
//   rowm/l/a[64]  : online softmax state
__global__ __launch_bounds__(256) void flash_kernel() {
    __shared__ float stage[64 * 33 * 2];      // 4224 floats
    __shared__ float Ps[64 * 65];             // 4160 floats
    __shared__ float rowm[64], rowl[64], rowa[64];

    float* Qs = stage;                // [64][33]
    float* Ks = stage + 64 * 33;      // [64][33]
    float* Vs = stage;                // [16][257] (reused)

    int b = blockIdx.y;
    int i0 = blockIdx.x * 64;
    const float* Qb = g_q + (size_t)b * N * C;
    const float* Kb = g_k + (size_t)b * N * C;
    const float* Vb = g_v + (size_t)b * N * C;

    int tid = threadIdx.x;
    int tx = tid & 15, ty = tid >> 4;

    // O fragment: rows 4*ty+ii (ii<4), cols tx + 16*cc (cc<16)
    float O[4][16];
#pragma unroll
    for (int i = 0; i < 4; i++)
#pragma unroll
        for (int j = 0; j < 16; j++) O[i][j] = 0.f;

    if (tid < 64) { rowm[tid] = -3.4e38f; rowl[tid] = 0.f; }
    __syncthreads();

    for (int j0 = 0; j0 < N; j0 += 64) {
        // ----- S = Q Kt (64x64), 4x4 fragment per thread -----
        float acc[4][4] = {};
        for (int k0 = 0; k0 < C; k0 += 32) {
            for (int i = tid; i < 64 * 32; i += 256) {
                int rr = i >> 5, cc = i & 31;
                Qs[rr * 33 + cc] = Qb[(size_t)(i0 + rr) * C + k0 + cc];
                Ks[rr * 33 + cc] = Kb[(size_t)(j0 + rr) * C + k0 + cc];
            }
            __syncthreads();
#pragma unroll
            for (int k = 0; k < 32; k++) {
                float a[4], bb[4];
#pragma unroll
                for (int i = 0; i < 4; i++) a[i] = Qs[(ty * 4 + i) * 33 + k];
#pragma unroll
                for (int j = 0; j < 4; j++) bb[j] = Ks[(tx * 4 + j) * 33 + k];
#pragma unroll
                for (int i = 0; i < 4; i++)
#pragma unroll
                    for (int j = 0; j < 4; j++) acc[i][j] += a[i] * bb[j];
            }
            __syncthreads();
        }
        // store scaled S
#pragma unroll
        for (int i = 0; i < 4; i++)
#pragma unroll
            for (int j = 0; j < 4; j++)
                Ps[(ty * 4 + i) * 65 + tx * 4 + j] = acc[i][j] * SCALE;
        __syncthreads();

        // ----- online softmax per row (threads 0..63) -----
        if (tid < 64) {
            float mprev = rowm[tid];
            float mx = mprev;
            float* pr = Ps + tid * 65;
#pragma unroll 8
            for (int j = 0; j < 64; j++) mx = fmaxf(mx, pr[j]);
            float alpha = __expf(mprev - mx);
            float s = 0.f;
#pragma unroll 8
            for (int j = 0; j < 64; j++) {
                float e = __expf(pr[j] - mx);
                pr[j] = e;
                s += e;
            }
            rowl[tid] = rowl[tid] * alpha + s;
            rowm[tid] = mx;
            rowa[tid] = alpha;
        }
        __syncthreads();

        // ----- O = O*alpha + P V, V streamed in 16-row chunks -----
        float al[4];
#pragma unroll
        for (int i = 0; i < 4; i++) al[i] = rowa[ty * 4 + i];
#pragma unroll
        for (int i = 0; i < 4; i++)
#pragma unroll
            for (int j = 0; j < 16; j++) O[i][j] *= al[i];

        for (int kc = 0; kc < 64; kc += 16) {
            // load V rows [j0+kc, j0+kc+16) x 256 into Vs (reuses Q/K stage)
            for (int i = tid; i < 16 * 256; i += 256) {
                int rr = i >> 8, cc = i & 255;
                Vs[rr * 257 + cc] = Vb[(size_t)(j0 + kc + rr) * C + cc];
            }
            __syncthreads();
#pragma unroll 4
            for (int k = 0; k < 16; k++) {
                float p[4], v[16];
#pragma unroll
                for (int i = 0; i < 4; i++) p[i] = Ps[(ty * 4 + i) * 65 + kc + k];
#pragma unroll
                for (int j = 0; j < 16; j++) v[j] = Vs[k * 257 + tx + 16 * j];
#pragma unroll
                for (int i = 0; i < 4; i++)
#pragma unroll
                    for (int j = 0; j < 16; j++) O[i][j] += p[i] * v[j];
            }
            __syncthreads();
        }
    }

    // finalize + write [b][n][c]
#pragma unroll
    for (int i = 0; i < 4; i++) {
        float inv = 1.0f / rowl[ty * 4 + i];
        float* dst = g_att + ((size_t)b * N + i0 + ty * 4 + i) * C + tx;
#pragma unroll
        for (int j = 0; j < 16; j++) dst[16 * j] = O[i][j] * inv;
    }
}

// ---------------- kernel 5: proj GEMM + bias + residual ----------------------
__global__ void proj_gemm(const float* __restrict__ W, const float* __restrict__ bias,
                          const float* __restrict__ x, float* __restrict__ out) {
    int b = blockIdx.z;
    int o0 = blockIdx.y * 64;
    int n0 = blockIdx.x * 64;
    __shared__ float As[64][33];    // [o][k]
    __shared__ float Bs[32][65];    // [k][n]
    const float* Ab = g_att + (size_t)b * N * C;
    float acc[4][4] = {};
    int tx = threadIdx.x & 15, ty = threadIdx.x >> 4;
    for (int k0 = 0; k0 < C; k0 += 32) {
        for (int i = threadIdx.x; i < 64 * 32; i += 256) {
            int rr = i >> 5, cc = i & 31;
            As[rr][cc] = W[(size_t)(o0 + rr) * C + k0 + cc];
        }
        for (int i = threadIdx.x; i < 64 * 32; i += 256) {
            int nn = i >> 5, cc = i & 31;   // att row n0+nn, channel k0+cc (contiguous)
            Bs[cc][nn] = Ab[(size_t)(n0 + nn) * C + k0 + cc];
        }
        __syncthreads();
#pragma unroll
        for (int k = 0; k < 32; k++) {
            float a[4], bb[4];
#pragma unroll
            for (int i = 0; i < 4; i++) a[i] = As[ty * 4 + i][k];
#pragma unroll
            for (int j = 0; j < 4; j++) bb[j] = Bs[k][tx * 4 + j];
#pragma unroll
            for (int i = 0; i < 4; i++)
#pragma unroll
                for (int j = 0; j < 4; j++) acc[i][j] += a[i] * bb[j];
        }
        __syncthreads();
    }
#pragma unroll
    for (int i = 0; i < 4; i++) {
        int o = o0 + ty * 4 + i;
        float bv = bias[o];
#pragma unroll
        for (int j = 0; j < 4; j++) {
            int n = n0 + tx * 4 + j;
            size_t idx = ((size_t)b * C + o) * N + n;
            out[idx] = acc[i][j] + bv + x[idx];
        }
    }
}

// ---------------- launch ------------------------------------------------------
extern "C" void kernel_launch(void* const* d_in, const int* in_sizes, int n_in,
                              void* d_out, int out_size) {
    const float* x    = (const float*)d_in[0];
    const float* gns  = (const float*)d_in[1];
    const float* gnb  = (const float*)d_in[2];
    const float* qkvw = (const float*)d_in[3];
    const float* qkvb = (const float*)d_in[4];
    const float* pw   = (const float*)d_in[5];
    const float* pb   = (const float*)d_in[6];
    float* out = (float*)d_out;

    gn_stats<<<B * G, 256>>>(x);
    gn_apply<<<(B * C * N / 4) / 256, 256>>>(x, gns, gnb);

    dim3 gq(N / 64, (3 * C) / 64, B);
    qkv_gemm<<<gq, 256>>>(qkvw, qkvb);

    dim3 gf(N / 64, B);
    flash_kernel<<<gf, 256>>>();

    dim3 gp(N / 64, C / 64, B);
    proj_gemm<<<gp, 256>>>(pw, pb, x, out);
}

// round 5
// speedup vs baseline: 2.4472x; 2.4472x over previous
#include <cuda_runtime.h>
#include <cstdint>

#define B 8
#define C 256
#define N 4096            // 64*64
#define G 8
#define CG 32             // channels per group
#define EPS 1e-5f
#define SCALE 0.0625f     // 1/sqrt(256)

// ---------------- scratch ----------------------------------------------------
__device__ float g_xn[(size_t)B * C * N];      // groupnormed x, [b][c][n]
__device__ float g_q[(size_t)B * N * C];       // Q [b][n][c]
__device__ float g_k[(size_t)B * N * C];       // K [b][n][c]
__device__ float g_v[(size_t)B * N * C];       // V [b][n][c]
__device__ float g_att[(size_t)B * N * C];     // attention out [b][n][c]
__device__ float g_mean[B * G];
__device__ float g_rstd[B * G];

// ---------------- mma helpers -------------------------------------------------
__device__ __forceinline__ uint32_t f2tf32(float x) {
    uint32_t r;
    asm("cvt.rna.tf32.f32 %0, %1;" : "=r"(r) : "f"(x));
    return r;
}

// D = A(16x8) * B(8x8) + C, tf32 inputs, fp32 accum. row.col.
__device__ __forceinline__ void mma_tf32(float* d, const uint32_t* a, const uint32_t* b) {
    asm volatile(
        "mma.sync.aligned.m16n8k8.row.col.f32.tf32.tf32.f32 "
        "{%0,%1,%2,%3}, {%4,%5,%6,%7}, {%8,%9}, {%0,%1,%2,%3};\n"
        : "+f"(d[0]), "+f"(d[1]), "+f"(d[2]), "+f"(d[3])
        : "r"(a[0]), "r"(a[1]), "r"(a[2]), "r"(a[3]),
          "r"(b[0]), "r"(b[1]));
}

// ---------------- kernel 1: groupnorm stats ----------------------------------
__global__ void gn_stats(const float* __restrict__ x) {
    int bg = blockIdx.x;
    const float4* p = (const float4*)(x + (size_t)bg * CG * N);
    float s = 0.f, ss = 0.f;
    for (int i = threadIdx.x; i < (CG * N) / 4; i += blockDim.x) {
        float4 v = p[i];
        s  += v.x + v.y + v.z + v.w;
        ss += v.x * v.x + v.y * v.y + v.z * v.z + v.w * v.w;
    }
    for (int o = 16; o > 0; o >>= 1) {
        s  += __shfl_down_sync(0xffffffffu, s, o);
        ss += __shfl_down_sync(0xffffffffu, ss, o);
    }
    __shared__ float rs[8], rss[8];
    int wid = threadIdx.x >> 5, lid = threadIdx.x & 31;
    if (lid == 0) { rs[wid] = s; rss[wid] = ss; }
    __syncthreads();
    if (threadIdx.x == 0) {
        float ts = 0.f, tss = 0.f;
        for (int i = 0; i < 8; i++) { ts += rs[i]; tss += rss[i]; }
        float inv = 1.0f / (float)(CG * N);
        float mean = ts * inv;
        float var = tss * inv - mean * mean;
        g_mean[bg] = mean;
        g_rstd[bg] = rsqrtf(var + EPS);
    }
}

// ---------------- kernel 2: groupnorm apply ----------------------------------
__global__ void gn_apply(const float* __restrict__ x,
                         const float* __restrict__ sc,
                         const float* __restrict__ bi) {
    int i = blockIdx.x * blockDim.x + threadIdx.x;
    int e = i << 2;
    int c = (e >> 12) & (C - 1);
    int bg = e >> 17;
    float m = g_mean[bg], r = g_rstd[bg];
    float a = sc[c] * r;
    float b = bi[c] - m * a;
    float4 v = ((const float4*)x)[i];
    float4 o;
    o.x = v.x * a + b; o.y = v.y * a + b; o.z = v.z * a + b; o.w = v.w * a + b;
    ((float4*)g_xn)[i] = o;
}

// ---------------- kernel 3: QKV GEMM, tf32 mma (768 x 4096 x 256 / batch) ----
// block: 64(o) x 64(n); 8 warps: warp w -> rows 16*(w&3), cols 32*(w>>2)
__global__ __launch_bounds__(256) void qkv_gemm(const float* __restrict__ W,
                                                const float* __restrict__ bias) {
    __shared__ uint32_t Ws[64 * 36];
    __shared__ uint32_t Xs[32 * 72];
    int b  = blockIdx.z;
    int o0 = blockIdx.y * 64;
    int n0 = blockIdx.x * 64;
    const float* Xb = g_xn + (size_t)b * C * N;

    int tid  = threadIdx.x;
    int warp = tid >> 5, lane = tid & 31;
    int gr = lane >> 2, t = lane & 3;
    int r0 = 16 * (warp & 3);
    int c0 = 32 * (warp >> 2);

    float acc[4][4] = {};
    for (int k0 = 0; k0 < C; k0 += 32) {
        for (int i = tid; i < 64 * 32; i += 256) {
            int rr = i >> 5, cc = i & 31;
            Ws[rr * 36 + cc] = f2tf32(W[(size_t)(o0 + rr) * C + k0 + cc]);
        }
        for (int i = tid; i < 32 * 64; i += 256) {
            int kk = i >> 6, nn = i & 63;
            Xs[kk * 72 + nn] = f2tf32(Xb[(size_t)(k0 + kk) * N + n0 + nn]);
        }
        __syncthreads();
#pragma unroll
        for (int ks = 0; ks < 4; ks++) {
            int kb = ks * 8;
            uint32_t a[4];
            a[0] = Ws[(r0 + gr) * 36 + kb + t];
            a[1] = Ws[(r0 + gr + 8) * 36 + kb + t];
            a[2] = Ws[(r0 + gr) * 36 + kb + t + 4];
            a[3] = Ws[(r0 + gr + 8) * 36 + kb + t + 4];
#pragma unroll
            for (int nt = 0; nt < 4; nt++) {
                int nb = c0 + nt * 8;
                uint32_t bb[2];
                bb[0] = Xs[(kb + t) * 72 + nb + gr];
                bb[1] = Xs[(kb + t + 4) * 72 + nb + gr];
                mma_tf32(acc[nt], a, bb);
            }
        }
        __syncthreads();
    }
    // epilogue: c0/c1 -> (row gr, n 2t/2t+1), c2/c3 -> (row gr+8)
    int o_a = o0 + r0 + gr, o_b = o_a + 8;
    float bv_a = bias[o_a], bv_b = bias[o_b];
    float* dst_a; int oc_a;
    if (o_a < 256)      { dst_a = g_q; oc_a = o_a; }
    else if (o_a < 512) { dst_a = g_k; oc_a = o_a - 256; }
    else                { dst_a = g_v; oc_a = o_a - 512; }
    float* dst_b; int oc_b;
    if (o_b < 256)      { dst_b = g_q; oc_b = o_b; }
    else if (o_b < 512) { dst_b = g_k; oc_b = o_b - 256; }
    else                { dst_b = g_v; oc_b = o_b - 512; }
#pragma unroll
    for (int nt = 0; nt < 4; nt++) {
        int n = n0 + c0 + nt * 8 + 2 * t;
        dst_a[((size_t)b * N + n)     * C + oc_a] = acc[nt][0] + bv_a;
        dst_a[((size_t)b * N + n + 1) * C + oc_a] = acc[nt][1] + bv_a;
        dst_b[((size_t)b * N + n)     * C + oc_b] = acc[nt][2] + bv_b;
        dst_b[((size_t)b * N + n + 1) * C + oc_b] = acc[nt][3] + bv_b;
    }
}

// ---------------- kernel 4: flash attention, tf32 mma -------------------------
// Br = Bc = 64, 256 threads (8 warps). Q/K/V in [b][n][c].
__global__ __launch_bounds__(256) void flash_kernel() {
    __shared__ uint32_t stage[2 * 64 * 36];   // Qs/Ks, reused as Vs[16][264]
    __shared__ float Ps[64 * 68];
    __shared__ float red[256];
    __shared__ float rowm[64], rowl[64], rowa[64];

    uint32_t* Qs = stage;
    uint32_t* Ks = stage + 64 * 36;
    uint32_t* Vs = stage;                     // 16*264 = 4224 <= 4608

    int b  = blockIdx.y;
    int i0 = blockIdx.x * 64;
    const float* Qb = g_q + (size_t)b * N * C;
    const float* Kb = g_k + (size_t)b * N * C;
    const float* Vb = g_v + (size_t)b * N * C;

    int tid  = threadIdx.x;
    int warp = tid >> 5, lane = tid & 31;
    int gr = lane >> 2, t = lane & 3;
    int r0 = 16 * (warp & 3);            // S & O row base
    int cs = 32 * (warp >> 2);           // S col base
    int co = 128 * (warp >> 2);          // O col base

    float acco[16][4];                   // O: 16 rows x 128 cols per warp
#pragma unroll
    for (int i = 0; i < 16; i++)
#pragma unroll
        for (int j = 0; j < 4; j++) acco[i][j] = 0.f;

    if (tid < 64) { rowm[tid] = -3.4e38f; rowl[tid] = 0.f; }
    __syncthreads();

    for (int j0 = 0; j0 < N; j0 += 64) {
        // ---------- S = Q K^T ----------
        float accs[4][4] = {};
        for (int k0 = 0; k0 < C; k0 += 32) {
            for (int i = tid; i < 64 * 32; i += 256) {
                int rr = i >> 5, cc = i & 31;
                Qs[rr * 36 + cc] = f2tf32(Qb[(size_t)(i0 + rr) * C + k0 + cc]);
                Ks[rr * 36 + cc] = f2tf32(Kb[(size_t)(j0 + rr) * C + k0 + cc]);
            }
            __syncthreads();
#pragma unroll
            for (int ks = 0; ks < 4; ks++) {
                int kb = ks * 8;
                uint32_t a[4];
                a[0] = Qs[(r0 + gr) * 36 + kb + t];
                a[1] = Qs[(r0 + gr + 8) * 36 + kb + t];
                a[2] = Qs[(r0 + gr) * 36 + kb + t + 4];
                a[3] = Qs[(r0 + gr + 8) * 36 + kb + t + 4];
#pragma unroll
                for (int nt = 0; nt < 4; nt++) {
                    int nb = cs + nt * 8;
                    uint32_t bb[2];
                    bb[0] = Ks[(nb + gr) * 36 + kb + t];
                    bb[1] = Ks[(nb + gr) * 36 + kb + t + 4];
                    mma_tf32(accs[nt], a, bb);
                }
            }
            __syncthreads();
        }
        // store scaled S tile -> Ps
#pragma unroll
        for (int nt = 0; nt < 4; nt++) {
            int col = cs + nt * 8 + 2 * t;
            float2 v0 = make_float2(accs[nt][0] * SCALE, accs[nt][1] * SCALE);
            float2 v1 = make_float2(accs[nt][2] * SCALE, accs[nt][3] * SCALE);
            *(float2*)&Ps[(r0 + gr) * 68 + col]     = v0;
            *(float2*)&Ps[(r0 + gr + 8) * 68 + col] = v1;
        }
        __syncthreads();

        // ---------- online softmax (256 threads, 4 segments of 16 cols) ------
        int row = tid & 63, seg = tid >> 6;
        {
            float mx = -3.4e38f;
#pragma unroll
            for (int j = 0; j < 16; j++) mx = fmaxf(mx, Ps[row * 68 + seg * 16 + j]);
            red[tid] = mx;
        }
        __syncthreads();
        if (tid < 64) {
            float m0 = fmaxf(fmaxf(red[tid], red[tid + 64]),
                             fmaxf(red[tid + 128], red[tid + 192]));
            float mprev = rowm[tid];
            float mnew  = fmaxf(mprev, m0);
            rowa[tid] = __expf(mprev - mnew);
            rowm[tid] = mnew;
        }
        __syncthreads();
        {
            float mnew = rowm[row];
            float s = 0.f;
#pragma unroll
            for (int j = 0; j < 16; j++) {
                int idx = row * 68 + seg * 16 + j;
                float e = __expf(Ps[idx] - mnew);
                Ps[idx] = e;
                s += e;
            }
            red[tid] = s;
        }
        __syncthreads();
        if (tid < 64)
            rowl[tid] = rowl[tid] * rowa[tid] +
                        (red[tid] + red[tid + 64] + red[tid + 128] + red[tid + 192]);
        __syncthreads();

        // ---------- O = O*alpha + P V ----------
        float al0 = rowa[r0 + gr], al1 = rowa[r0 + gr + 8];
#pragma unroll
        for (int nt = 0; nt < 16; nt++) {
            acco[nt][0] *= al0; acco[nt][1] *= al0;
            acco[nt][2] *= al1; acco[nt][3] *= al1;
        }

        for (int vc = 0; vc < 4; vc++) {
            for (int i = tid; i < 16 * 256; i += 256) {
                int rr = i >> 8, cc = i & 255;
                Vs[rr * 264 + cc] = f2tf32(Vb[(size_t)(j0 + vc * 16 + rr) * C + cc]);
            }
            __syncthreads();
#pragma unroll
            for (int ks = 0; ks < 2; ks++) {
                int kb = ks * 8;
                int pk = vc * 16 + kb;
                uint32_t a[4];
                a[0] = f2tf32(Ps[(r0 + gr) * 68 + pk + t]);
                a[1] = f2tf32(Ps[(r0 + gr + 8) * 68 + pk + t]);
                a[2] = f2tf32(Ps[(r0 + gr) * 68 + pk + t + 4]);
                a[3] = f2tf32(Ps[(r0 + gr + 8) * 68 + pk + t + 4]);
#pragma unroll
                for (int nt = 0; nt < 16; nt++) {
                    int nb = co + nt * 8;
                    uint32_t bb[2];
                    bb[0] = Vs[(kb + t) * 264 + nb + gr];
                    bb[1] = Vs[(kb + t + 4) * 264 + nb + gr];
                    mma_tf32(acco[nt], a, bb);
                }
            }
            __syncthreads();
        }
    }

    // ---------- finalize ----------
    float inv0 = 1.0f / rowl[r0 + gr];
    float inv1 = 1.0f / rowl[r0 + gr + 8];
    float* Ab = g_att + (size_t)b * N * C;
#pragma unroll
    for (int nt = 0; nt < 16; nt++) {
        int col = co + nt * 8 + 2 * t;
        float2 v0 = make_float2(acco[nt][0] * inv0, acco[nt][1] * inv0);
        float2 v1 = make_float2(acco[nt][2] * inv1, acco[nt][3] * inv1);
        *(float2*)&Ab[(size_t)(i0 + r0 + gr) * C + col]     = v0;
        *(float2*)&Ab[(size_t)(i0 + r0 + gr + 8) * C + col] = v1;
    }
}

// ---------------- kernel 5: proj GEMM + bias + residual, tf32 mma ------------
__global__ __launch_bounds__(256) void proj_gemm(const float* __restrict__ W,
                                                 const float* __restrict__ bias,
                                                 const float* __restrict__ x,
                                                 float* __restrict__ out) {
    __shared__ uint32_t Ws[64 * 36];
    __shared__ uint32_t Bs[32 * 68];
    int b  = blockIdx.z;
    int o0 = blockIdx.y * 64;
    int n0 = blockIdx.x * 64;
    const float* Ab = g_att + (size_t)b * N * C;

    int tid  = threadIdx.x;
    int warp = tid >> 5, lane = tid & 31;
    int gr = lane >> 2, t = lane & 3;
    int r0 = 16 * (warp & 3);
    int c0 = 32 * (warp >> 2);

    float acc[4][4] = {};
    for (int k0 = 0; k0 < C; k0 += 32) {
        for (int i = tid; i < 64 * 32; i += 256) {
            int rr = i >> 5, cc = i & 31;
            Ws[rr * 36 + cc] = f2tf32(W[(size_t)(o0 + rr) * C + k0 + cc]);
        }
        for (int i = tid; i < 64 * 32; i += 256) {
            int nn = i >> 5, kk = i & 31;   // coalesced read of att[n][c]
            Bs[kk * 68 + nn] = f2tf32(Ab[(size_t)(n0 + nn) * C + k0 + kk]);
        }
        __syncthreads();
#pragma unroll
        for (int ks = 0; ks < 4; ks++) {
            int kb = ks * 8;
            uint32_t a[4];
            a[0] = Ws[(r0 + gr) * 36 + kb + t];
            a[1] = Ws[(r0 + gr + 8) * 36 + kb + t];
            a[2] = Ws[(r0 + gr) * 36 + kb + t + 4];
            a[3] = Ws[(r0 + gr + 8) * 36 + kb + t + 4];
#pragma unroll
            for (int nt = 0; nt < 4; nt++) {
                int nb = c0 + nt * 8;
                uint32_t bb[2];
                bb[0] = Bs[(kb + t) * 68 + nb + gr];
                bb[1] = Bs[(kb + t + 4) * 68 + nb + gr];
                mma_tf32(acc[nt], a, bb);
            }
        }
        __syncthreads();
    }
    // epilogue: out[b][o][n] = acc + bias + x ; float2 along n
    int o_a = o0 + r0 + gr, o_b = o_a + 8;
    float bv_a = bias[o_a], bv_b = bias[o_b];
#pragma unroll
    for (int nt = 0; nt < 4; nt++) {
        int n = n0 + c0 + nt * 8 + 2 * t;
        size_t ia = ((size_t)b * C + o_a) * N + n;
        size_t ib = ((size_t)b * C + o_b) * N + n;
        float2 xa = *(const float2*)&x[ia];
        float2 xb = *(const float2*)&x[ib];
        float2 oa = make_float2(acc[nt][0] + bv_a + xa.x, acc[nt][1] + bv_a + xa.y);
        float2 ob = make_float2(acc[nt][2] + bv_b + xb.x, acc[nt][3] + bv_b + xb.y);
        *(float2*)&out[ia] = oa;
        *(float2*)&out[ib] = ob;
    }
}

// ---------------- launch ------------------------------------------------------
extern "C" void kernel_launch(void* const* d_in, const int* in_sizes, int n_in,
                              void* d_out, int out_size) {
    const float* x    = (const float*)d_in[0];
    const float* gns  = (const float*)d_in[1];
    const float* gnb  = (const float*)d_in[2];
    const float* qkvw = (const float*)d_in[3];
    const float* qkvb = (const float*)d_in[4];
    const float* pw   = (const float*)d_in[5];
    const float* pb   = (const float*)d_in[6];
    float* out = (float*)d_out;

    gn_stats<<<B * G, 256>>>(x);
    gn_apply<<<(B * C * N / 4) / 256, 256>>>(x, gns, gnb);

    dim3 gq(N / 64, (3 * C) / 64, B);
    qkv_gemm<<<gq, 256>>>(qkvw, qkvb);

    dim3 gf(N / 64, B);
    flash_kernel<<<gf, 256>>>();

    dim3 gp(N / 64, C / 64, B);
    proj_gemm<<<gp, 256>>>(pw, pb, x, out);
}

// round 6
// speedup vs baseline: 2.7425x; 1.1207x over previous
#include <cuda_runtime.h>
#include <cstdint>

#define B 8
#define C 256
#define N 4096            // 64*64
#define G 8
#define CG 32             // channels per group
#define EPS 1e-5f
#define SCALE 0.0625f     // 1/sqrt(256)

// ---------------- scratch ----------------------------------------------------
__device__ float    g_xn[(size_t)B * C * N];   // groupnormed x, [b][c][n]
__device__ uint32_t g_q[(size_t)B * N * C];    // Q [b][n][c], tf32 bits
__device__ uint32_t g_k[(size_t)B * N * C];    // K [b][n][c], tf32 bits
__device__ uint32_t g_v[(size_t)B * N * C];    // V [b][n][c], tf32 bits
__device__ float    g_att[(size_t)B * N * C];  // attention out [b][n][c]
__device__ float    g_mean[B * G];
__device__ float    g_rstd[B * G];

// ---------------- mma helpers -------------------------------------------------
__device__ __forceinline__ uint32_t f2tf32(float x) {
    uint32_t r;
    asm("cvt.rna.tf32.f32 %0, %1;" : "=r"(r) : "f"(x));
    return r;
}

// D = A(16x8) * B(8x8) + C, tf32 inputs, fp32 accum. row.col.
__device__ __forceinline__ void mma_tf32(float* d, const uint32_t* a, const uint32_t* b) {
    asm volatile(
        "mma.sync.aligned.m16n8k8.row.col.f32.tf32.tf32.f32 "
        "{%0,%1,%2,%3}, {%4,%5,%6,%7}, {%8,%9}, {%0,%1,%2,%3};\n"
        : "+f"(d[0]), "+f"(d[1]), "+f"(d[2]), "+f"(d[3])
        : "r"(a[0]), "r"(a[1]), "r"(a[2]), "r"(a[3]),
          "r"(b[0]), "r"(b[1]));
}

// ---------------- kernel 1: groupnorm stats ----------------------------------
__global__ void gn_stats(const float* __restrict__ x) {
    int bg = blockIdx.x;
    const float4* p = (const float4*)(x + (size_t)bg * CG * N);
    float s = 0.f, ss = 0.f;
    for (int i = threadIdx.x; i < (CG * N) / 4; i += blockDim.x) {
        float4 v = p[i];
        s  += v.x + v.y + v.z + v.w;
        ss += v.x * v.x + v.y * v.y + v.z * v.z + v.w * v.w;
    }
    for (int o = 16; o > 0; o >>= 1) {
        s  += __shfl_down_sync(0xffffffffu, s, o);
        ss += __shfl_down_sync(0xffffffffu, ss, o);
    }
    __shared__ float rs[8], rss[8];
    int wid = threadIdx.x >> 5, lid = threadIdx.x & 31;
    if (lid == 0) { rs[wid] = s; rss[wid] = ss; }
    __syncthreads();
    if (threadIdx.x == 0) {
        float ts = 0.f, tss = 0.f;
        for (int i = 0; i < 8; i++) { ts += rs[i]; tss += rss[i]; }
        float inv = 1.0f / (float)(CG * N);
        float mean = ts * inv;
        float var = tss * inv - mean * mean;
        g_mean[bg] = mean;
        g_rstd[bg] = rsqrtf(var + EPS);
    }
}

// ---------------- kernel 2: groupnorm apply ----------------------------------
__global__ void gn_apply(const float* __restrict__ x,
                         const float* __restrict__ sc,
                         const float* __restrict__ bi) {
    int i = blockIdx.x * blockDim.x + threadIdx.x;
    int e = i << 2;
    int c = (e >> 12) & (C - 1);
    int bg = e >> 17;
    float m = g_mean[bg], r = g_rstd[bg];
    float a = sc[c] * r;
    float b = bi[c] - m * a;
    float4 v = ((const float4*)x)[i];
    float4 o;
    o.x = v.x * a + b; o.y = v.y * a + b; o.z = v.z * a + b; o.w = v.w * a + b;
    ((float4*)g_xn)[i] = o;
}

// ---------------- kernel 3: QKV GEMM, tf32 mma; writes tf32 bits -------------
__global__ __launch_bounds__(256) void qkv_gemm(const float* __restrict__ W,
                                                const float* __restrict__ bias) {
    __shared__ uint32_t Ws[64 * 36];
    __shared__ uint32_t Xs[32 * 72];
    int b  = blockIdx.z;
    int o0 = blockIdx.y * 64;
    int n0 = blockIdx.x * 64;
    const float* Xb = g_xn + (size_t)b * C * N;

    int tid  = threadIdx.x;
    int warp = tid >> 5, lane = tid & 31;
    int gr = lane >> 2, t = lane & 3;
    int r0 = 16 * (warp & 3);
    int c0 = 32 * (warp >> 2);

    float acc[4][4] = {};
    for (int k0 = 0; k0 < C; k0 += 32) {
        for (int i = tid; i < 64 * 32; i += 256) {
            int rr = i >> 5, cc = i & 31;
            Ws[rr * 36 + cc] = f2tf32(W[(size_t)(o0 + rr) * C + k0 + cc]);
        }
        for (int i = tid; i < 32 * 64; i += 256) {
            int kk = i >> 6, nn = i & 63;
            Xs[kk * 72 + nn] = f2tf32(Xb[(size_t)(k0 + kk) * N + n0 + nn]);
        }
        __syncthreads();
#pragma unroll
        for (int ks = 0; ks < 4; ks++) {
            int kb = ks * 8;
            uint32_t a[4];
            a[0] = Ws[(r0 + gr) * 36 + kb + t];
            a[1] = Ws[(r0 + gr + 8) * 36 + kb + t];
            a[2] = Ws[(r0 + gr) * 36 + kb + t + 4];
            a[3] = Ws[(r0 + gr + 8) * 36 + kb + t + 4];
#pragma unroll
            for (int nt = 0; nt < 4; nt++) {
                int nb = c0 + nt * 8;
                uint32_t bb[2];
                bb[0] = Xs[(kb + t) * 72 + nb + gr];
                bb[1] = Xs[(kb + t + 4) * 72 + nb + gr];
                mma_tf32(acc[nt], a, bb);
            }
        }
        __syncthreads();
    }
    // epilogue: store tf32 bits
    int o_a = o0 + r0 + gr, o_b = o_a + 8;
    float bv_a = bias[o_a], bv_b = bias[o_b];
    uint32_t* dst_a; int oc_a;
    if (o_a < 256)      { dst_a = g_q; oc_a = o_a; }
    else if (o_a < 512) { dst_a = g_k; oc_a = o_a - 256; }
    else                { dst_a = g_v; oc_a = o_a - 512; }
    uint32_t* dst_b; int oc_b;
    if (o_b < 256)      { dst_b = g_q; oc_b = o_b; }
    else if (o_b < 512) { dst_b = g_k; oc_b = o_b - 256; }
    else                { dst_b = g_v; oc_b = o_b - 512; }
#pragma unroll
    for (int nt = 0; nt < 4; nt++) {
        int n = n0 + c0 + nt * 8 + 2 * t;
        dst_a[((size_t)b * N + n)     * C + oc_a] = f2tf32(acc[nt][0] + bv_a);
        dst_a[((size_t)b * N + n + 1) * C + oc_a] = f2tf32(acc[nt][1] + bv_a);
        dst_b[((size_t)b * N + n)     * C + oc_b] = f2tf32(acc[nt][2] + bv_b);
        dst_b[((size_t)b * N + n + 1) * C + oc_b] = f2tf32(acc[nt][3] + bv_b);
    }
}

// ---------------- kernel 4: flash attention, tf32 mma -------------------------
// Br = Bc = 64, 256 threads (8 warps). Q/K/V pre-converted tf32 in gmem.
__global__ __launch_bounds__(256) void flash_kernel() {
    __shared__ uint32_t stage[2 * 64 * 36];   // Qs/Ks; reused as Vs[16][264]
    __shared__ uint32_t Ps[64 * 68];          // S (float bits) then P (tf32 bits)
    __shared__ float rowm[64], rowl[64], rowa[64];

    uint32_t* Qs = stage;
    uint32_t* Ks = stage + 64 * 36;
    uint32_t* Vs = stage;                     // 16*264 = 4224 <= 4608

    int b  = blockIdx.y;
    int i0 = blockIdx.x * 64;
    const uint32_t* Qb = g_q + (size_t)b * N * C;
    const uint32_t* Kb = g_k + (size_t)b * N * C;
    const uint32_t* Vb = g_v + (size_t)b * N * C;

    int tid  = threadIdx.x;
    int warp = tid >> 5, lane = tid & 31;
    int gr = lane >> 2, t = lane & 3;
    int r0 = 16 * (warp & 3);            // S & O row base
    int cs = 32 * (warp >> 2);           // S col base
    int co = 128 * (warp >> 2);          // O col base

    int smrow = tid >> 2, smseg = tid & 3;   // softmax mapping (4 lanes/row)

    float acco[16][4];
#pragma unroll
    for (int i = 0; i < 16; i++)
#pragma unroll
        for (int j = 0; j < 4; j++) acco[i][j] = 0.f;

    if (tid < 64) { rowm[tid] = -3.4e38f; rowl[tid] = 0.f; }
    __syncthreads();

    for (int j0 = 0; j0 < N; j0 += 64) {
        // ---------- S = Q K^T ----------
        float accs[4][4] = {};
        for (int k0 = 0; k0 < C; k0 += 32) {
            // stage Q,K chunk as uint4 (already tf32)
            for (int i = tid; i < 512; i += 256) {
                int rr = i >> 3, cc = i & 7;
                ((uint4*)(Qs + rr * 36))[cc] =
                    ((const uint4*)(Qb + (size_t)(i0 + rr) * C + k0))[cc];
                ((uint4*)(Ks + rr * 36))[cc] =
                    ((const uint4*)(Kb + (size_t)(j0 + rr) * C + k0))[cc];
            }
            __syncthreads();
#pragma unroll
            for (int ks = 0; ks < 4; ks++) {
                int kb = ks * 8;
                uint32_t a[4];
                a[0] = Qs[(r0 + gr) * 36 + kb + t];
                a[1] = Qs[(r0 + gr + 8) * 36 + kb + t];
                a[2] = Qs[(r0 + gr) * 36 + kb + t + 4];
                a[3] = Qs[(r0 + gr + 8) * 36 + kb + t + 4];
#pragma unroll
                for (int nt = 0; nt < 4; nt++) {
                    int nb = cs + nt * 8;
                    uint32_t bb[2];
                    bb[0] = Ks[(nb + gr) * 36 + kb + t];
                    bb[1] = Ks[(nb + gr) * 36 + kb + t + 4];
                    mma_tf32(accs[nt], a, bb);
                }
            }
            __syncthreads();
        }
        // store scaled S tile (float bits) -> Ps
#pragma unroll
        for (int nt = 0; nt < 4; nt++) {
            int col = cs + nt * 8 + 2 * t;
            float2 v0 = make_float2(accs[nt][0] * SCALE, accs[nt][1] * SCALE);
            float2 v1 = make_float2(accs[nt][2] * SCALE, accs[nt][3] * SCALE);
            *(float2*)&Ps[(r0 + gr) * 68 + col]     = v0;
            *(float2*)&Ps[(r0 + gr + 8) * 68 + col] = v1;
        }
        __syncthreads();

        // ---------- fused online softmax (4 adjacent lanes per row) ----------
        {
            float mprev = rowm[smrow];
            float vals[16];
            float mx = mprev;
            uint32_t* pr = Ps + smrow * 68 + smseg * 16;
#pragma unroll
            for (int j = 0; j < 16; j++) {
                vals[j] = __uint_as_float(pr[j]);
                mx = fmaxf(mx, vals[j]);
            }
            mx = fmaxf(mx, __shfl_xor_sync(0xffffffffu, mx, 1));
            mx = fmaxf(mx, __shfl_xor_sync(0xffffffffu, mx, 2));
            float s = 0.f;
#pragma unroll
            for (int j = 0; j < 16; j++) {
                float e = __expf(vals[j] - mx);
                s += e;
                pr[j] = f2tf32(e);           // P as tf32 bits
            }
            s += __shfl_xor_sync(0xffffffffu, s, 1);
            s += __shfl_xor_sync(0xffffffffu, s, 2);
            if (smseg == 0) {
                float alpha = __expf(mprev - mx);
                rowa[smrow] = alpha;
                rowm[smrow] = mx;
                rowl[smrow] = rowl[smrow] * alpha + s;
            }
        }
        __syncthreads();

        // ---------- O = O*alpha + P V ----------
        float al0 = rowa[r0 + gr], al1 = rowa[r0 + gr + 8];
#pragma unroll
        for (int nt = 0; nt < 16; nt++) {
            acco[nt][0] *= al0; acco[nt][1] *= al0;
            acco[nt][2] *= al1; acco[nt][3] *= al1;
        }

        for (int vc = 0; vc < 4; vc++) {
            // stage V chunk (16 x 256) as uint4
            for (int i = tid; i < 1024; i += 256) {
                int rr = i >> 6, cc = i & 63;
                ((uint4*)(Vs + rr * 264))[cc] =
                    ((const uint4*)(Vb + (size_t)(j0 + vc * 16 + rr) * C))[cc];
            }
            __syncthreads();
#pragma unroll
            for (int ks = 0; ks < 2; ks++) {
                int kb = ks * 8;
                int pk = vc * 16 + kb;
                uint32_t a[4];
                a[0] = Ps[(r0 + gr) * 68 + pk + t];
                a[1] = Ps[(r0 + gr + 8) * 68 + pk + t];
                a[2] = Ps[(r0 + gr) * 68 + pk + t + 4];
                a[3] = Ps[(r0 + gr + 8) * 68 + pk + t + 4];
#pragma unroll
                for (int nt = 0; nt < 16; nt++) {
                    int nb = co + nt * 8;
                    uint32_t bb[2];
                    bb[0] = Vs[(kb + t) * 264 + nb + gr];
                    bb[1] = Vs[(kb + t + 4) * 264 + nb + gr];
                    mma_tf32(acco[nt], a, bb);
                }
            }
            __syncthreads();
        }
    }

    // ---------- finalize ----------
    float inv0 = 1.0f / rowl[r0 + gr];
    float inv1 = 1.0f / rowl[r0 + gr + 8];
    float* Ab = g_att + (size_t)b * N * C;
#pragma unroll
    for (int nt = 0; nt < 16; nt++) {
        int col = co + nt * 8 + 2 * t;
        float2 v0 = make_float2(acco[nt][0] * inv0, acco[nt][1] * inv0);
        float2 v1 = make_float2(acco[nt][2] * inv1, acco[nt][3] * inv1);
        *(float2*)&Ab[(size_t)(i0 + r0 + gr) * C + col]     = v0;
        *(float2*)&Ab[(size_t)(i0 + r0 + gr + 8) * C + col] = v1;
    }
}

// ---------------- kernel 5: proj GEMM + bias + residual, tf32 mma ------------
__global__ __launch_bounds__(256) void proj_gemm(const float* __restrict__ W,
                                                 const float* __restrict__ bias,
                                                 const float* __restrict__ x,
                                                 float* __restrict__ out) {
    __shared__ uint32_t Ws[64 * 36];
    __shared__ uint32_t Bs[32 * 68];
    int b  = blockIdx.z;
    int o0 = blockIdx.y * 64;
    int n0 = blockIdx.x * 64;
    const float* Ab = g_att + (size_t)b * N * C;

    int tid  = threadIdx.x;
    int warp = tid >> 5, lane = tid & 31;
    int gr = lane >> 2, t = lane & 3;
    int r0 = 16 * (warp & 3);
    int c0 = 32 * (warp >> 2);

    float acc[4][4] = {};
    for (int k0 = 0; k0 < C; k0 += 32) {
        for (int i = tid; i < 64 * 32; i += 256) {
            int rr = i >> 5, cc = i & 31;
            Ws[rr * 36 + cc] = f2tf32(W[(size_t)(o0 + rr) * C + k0 + cc]);
        }
        for (int i = tid; i < 64 * 32; i += 256) {
            int nn = i >> 5, kk = i & 31;
            Bs[kk * 68 + nn] = f2tf32(Ab[(size_t)(n0 + nn) * C + k0 + kk]);
        }
        __syncthreads();
#pragma unroll
        for (int ks = 0; ks < 4; ks++) {
            int kb = ks * 8;
            uint32_t a[4];
            a[0] = Ws[(r0 + gr) * 36 + kb + t];
            a[1] = Ws[(r0 + gr + 8) * 36 + kb + t];
            a[2] = Ws[(r0 + gr) * 36 + kb + t + 4];
            a[3] = Ws[(r0 + gr + 8) * 36 + kb + t + 4];
#pragma unroll
            for (int nt = 0; nt < 4; nt++) {
                int nb = c0 + nt * 8;
                uint32_t bb[2];
                bb[0] = Bs[(kb + t) * 68 + nb + gr];
                bb[1] = Bs[(kb + t + 4) * 68 + nb + gr];
                mma_tf32(acc[nt], a, bb);
            }
        }
        __syncthreads();
    }
    int o_a = o0 + r0 + gr, o_b = o_a + 8;
    float bv_a = bias[o_a], bv_b = bias[o_b];
#pragma unroll
    for (int nt = 0; nt < 4; nt++) {
        int n = n0 + c0 + nt * 8 + 2 * t;
        size_t ia = ((size_t)b * C + o_a) * N + n;
        size_t ib = ((size_t)b * C + o_b) * N + n;
        float2 xa = *(const float2*)&x[ia];
        float2 xb = *(const float2*)&x[ib];
        float2 oa = make_float2(acc[nt][0] + bv_a + xa.x, acc[nt][1] + bv_a + xa.y);
        float2 ob = make_float2(acc[nt][2] + bv_b + xb.x, acc[nt][3] + bv_b + xb.y);
        *(float2*)&out[ia] = oa;
        *(float2*)&out[ib] = ob;
    }
}

// ---------------- launch ------------------------------------------------------
extern "C" void kernel_launch(void* const* d_in, const int* in_sizes, int n_in,
                              void* d_out, int out_size) {
    const float* x    = (const float*)d_in[0];
    const float* gns  = (const float*)d_in[1];
    const float* gnb  = (const float*)d_in[2];
    const float* qkvw = (const float*)d_in[3];
    const float* qkvb = (const float*)d_in[4];
    const float* pw   = (const float*)d_in[5];
    const float* pb   = (const float*)d_in[6];
    float* out = (float*)d_out;

    gn_stats<<<B * G, 256>>>(x);
    gn_apply<<<(B * C * N / 4) / 256, 256>>>(x, gns, gnb);

    dim3 gq(N / 64, (3 * C) / 64, B);
    qkv_gemm<<<gq, 256>>>(qkvw, qkvb);

    dim3 gf(N / 64, B);
    flash_kernel<<<gf, 256>>>();

    dim3 gp(N / 64, C / 64, B);
    proj_gemm<<<gp, 256>>>(pw, pb, x, out);
}

// round 7
// speedup vs baseline: 5.1465x; 1.8765x over previous
#include <cuda_runtime.h>
#include <cuda_bf16.h>
#include <cstdint>

#define B 8
#define C 256
#define N 4096            // 64*64
#define G 8
#define CG 32             // channels per group
#define EPS 1e-5f
#define SCALE 0.0625f     // 1/sqrt(256)

// ---------------- scratch ----------------------------------------------------
__device__ float         g_xn[(size_t)B * C * N];   // groupnormed x, [b][c][n]
__device__ __nv_bfloat16 g_q[(size_t)B * N * C];    // Q [b][n][c]
__device__ __nv_bfloat16 g_k[(size_t)B * N * C];    // K [b][n][c]
__device__ __nv_bfloat16 g_v[(size_t)B * C * N];    // V [b][c][n]  (transposed!)
__device__ float         g_att[(size_t)B * N * C];  // attention out [b][n][c]
__device__ float         g_mean[B * G];
__device__ float         g_rstd[B * G];

// ---------------- mma helpers -------------------------------------------------
__device__ __forceinline__ uint32_t f2tf32(float x) {
    uint32_t r;
    asm("cvt.rna.tf32.f32 %0, %1;" : "=r"(r) : "f"(x));
    return r;
}

// tf32: D = A(16x8) * B(8x8) + C
__device__ __forceinline__ void mma_tf32(float* d, const uint32_t* a, const uint32_t* b) {
    asm volatile(
        "mma.sync.aligned.m16n8k8.row.col.f32.tf32.tf32.f32 "
        "{%0,%1,%2,%3}, {%4,%5,%6,%7}, {%8,%9}, {%0,%1,%2,%3};\n"
        : "+f"(d[0]), "+f"(d[1]), "+f"(d[2]), "+f"(d[3])
        : "r"(a[0]), "r"(a[1]), "r"(a[2]), "r"(a[3]),
          "r"(b[0]), "r"(b[1]));
}

// bf16: D = A(16x16) * B(16x8) + C
__device__ __forceinline__ void mma_bf16(float* d, const uint32_t* a, const uint32_t* b) {
    asm volatile(
        "mma.sync.aligned.m16n8k16.row.col.f32.bf16.bf16.f32 "
        "{%0,%1,%2,%3}, {%4,%5,%6,%7}, {%8,%9}, {%0,%1,%2,%3};\n"
        : "+f"(d[0]), "+f"(d[1]), "+f"(d[2]), "+f"(d[3])
        : "r"(a[0]), "r"(a[1]), "r"(a[2]), "r"(a[3]),
          "r"(b[0]), "r"(b[1]));
}

// ---------------- kernel 1: groupnorm stats ----------------------------------
__global__ void gn_stats(const float* __restrict__ x) {
    int bg = blockIdx.x;
    const float4* p = (const float4*)(x + (size_t)bg * CG * N);
    float s = 0.f, ss = 0.f;
    for (int i = threadIdx.x; i < (CG * N) / 4; i += blockDim.x) {
        float4 v = p[i];
        s  += v.x + v.y + v.z + v.w;
        ss += v.x * v.x + v.y * v.y + v.z * v.z + v.w * v.w;
    }
    for (int o = 16; o > 0; o >>= 1) {
        s  += __shfl_down_sync(0xffffffffu, s, o);
        ss += __shfl_down_sync(0xffffffffu, ss, o);
    }
    __shared__ float rs[8], rss[8];
    int wid = threadIdx.x >> 5, lid = threadIdx.x & 31;
    if (lid == 0) { rs[wid] = s; rss[wid] = ss; }
    __syncthreads();
    if (threadIdx.x == 0) {
        float ts = 0.f, tss = 0.f;
        for (int i = 0; i < 8; i++) { ts += rs[i]; tss += rss[i]; }
        float inv = 1.0f / (float)(CG * N);
        float mean = ts * inv;
        float var = tss * inv - mean * mean;
        g_mean[bg] = mean;
        g_rstd[bg] = rsqrtf(var + EPS);
    }
}

// ---------------- kernel 2: groupnorm apply ----------------------------------
__global__ void gn_apply(const float* __restrict__ x,
                         const float* __restrict__ sc,
                         const float* __restrict__ bi) {
    int i = blockIdx.x * blockDim.x + threadIdx.x;
    int e = i << 2;
    int c = (e >> 12) & (C - 1);
    int bg = e >> 17;
    float m = g_mean[bg], r = g_rstd[bg];
    float a = sc[c] * r;
    float b = bi[c] - m * a;
    float4 v = ((const float4*)x)[i];
    float4 o;
    o.x = v.x * a + b; o.y = v.y * a + b; o.z = v.z * a + b; o.w = v.w * a + b;
    ((float4*)g_xn)[i] = o;
}

// ---------------- kernel 3: QKV GEMM, tf32 mma; writes bf16 ------------------
__global__ __launch_bounds__(256) void qkv_gemm(const float* __restrict__ W,
                                                const float* __restrict__ bias) {
    __shared__ uint32_t Ws[64 * 36];
    __shared__ uint32_t Xs[32 * 72];
    int b  = blockIdx.z;
    int o0 = blockIdx.y * 64;
    int n0 = blockIdx.x * 64;
    const float* Xb = g_xn + (size_t)b * C * N;

    int tid  = threadIdx.x;
    int warp = tid >> 5, lane = tid & 31;
    int gr = lane >> 2, t = lane & 3;
    int r0 = 16 * (warp & 3);
    int c0 = 32 * (warp >> 2);

    float acc[4][4] = {};
    for (int k0 = 0; k0 < C; k0 += 32) {
        for (int i = tid; i < 64 * 32; i += 256) {
            int rr = i >> 5, cc = i & 31;
            Ws[rr * 36 + cc] = f2tf32(W[(size_t)(o0 + rr) * C + k0 + cc]);
        }
        for (int i = tid; i < 32 * 64; i += 256) {
            int kk = i >> 6, nn = i & 63;
            Xs[kk * 72 + nn] = f2tf32(Xb[(size_t)(k0 + kk) * N + n0 + nn]);
        }
        __syncthreads();
#pragma unroll
        for (int ks = 0; ks < 4; ks++) {
            int kb = ks * 8;
            uint32_t a[4];
            a[0] = Ws[(r0 + gr) * 36 + kb + t];
            a[1] = Ws[(r0 + gr + 8) * 36 + kb + t];
            a[2] = Ws[(r0 + gr) * 36 + kb + t + 4];
            a[3] = Ws[(r0 + gr + 8) * 36 + kb + t + 4];
#pragma unroll
            for (int nt = 0; nt < 4; nt++) {
                int nb = c0 + nt * 8;
                uint32_t bb[2];
                bb[0] = Xs[(kb + t) * 72 + nb + gr];
                bb[1] = Xs[(kb + t + 4) * 72 + nb + gr];
                mma_tf32(acc[nt], a, bb);
            }
        }
        __syncthreads();
    }
    // epilogue
    int o_a = o0 + r0 + gr, o_b = o_a + 8;
    float bv_a = bias[o_a], bv_b = bias[o_b];
    if (o0 < 512) {
        // Q or K: layout [b][n][c], bf16 scattered stores
        __nv_bfloat16* dst = (o0 < 256) ? g_q : g_k;
        int oc_a = o_a & 255, oc_b = o_b & 255;
#pragma unroll
        for (int nt = 0; nt < 4; nt++) {
            int n = n0 + c0 + nt * 8 + 2 * t;
            dst[((size_t)b * N + n)     * C + oc_a] = __float2bfloat16(acc[nt][0] + bv_a);
            dst[((size_t)b * N + n + 1) * C + oc_a] = __float2bfloat16(acc[nt][1] + bv_a);
            dst[((size_t)b * N + n)     * C + oc_b] = __float2bfloat16(acc[nt][2] + bv_b);
            dst[((size_t)b * N + n + 1) * C + oc_b] = __float2bfloat16(acc[nt][3] + bv_b);
        }
    } else {
        // V: layout [b][c][n], bf16x2 stores along n
        int oc_a = o_a - 512, oc_b = o_b - 512;
#pragma unroll
        for (int nt = 0; nt < 4; nt++) {
            int n = n0 + c0 + nt * 8 + 2 * t;
            __nv_bfloat162 va = __floats2bfloat162_rn(acc[nt][0] + bv_a, acc[nt][1] + bv_a);
            __nv_bfloat162 vb = __floats2bfloat162_rn(acc[nt][2] + bv_b, acc[nt][3] + bv_b);
            *(__nv_bfloat162*)&g_v[((size_t)b * C + oc_a) * N + n] = va;
            *(__nv_bfloat162*)&g_v[((size_t)b * C + oc_b) * N + n] = vb;
        }
    }
}

// ---------------- kernel 4: flash attention, bf16 mma -------------------------
// Br = Bc = 64, 256 threads (8 warps).
// Smem: QKs (Q+K chunk, bf16 pairs, stride 36 u32) 18.4KB
//       PsVs: S fp32 [64][68]  aliased with  V stage [256][17] (both 4352 u32)
//       Pp: packed bf16 P [64][36] 9.2KB
__global__ __launch_bounds__(256) void flash_kernel() {
    __shared__ uint32_t QKs[2 * 64 * 36];
    __shared__ uint32_t PsVs[64 * 68];
    __shared__ uint32_t Pp[64 * 36];
    __shared__ float rowm[64], rowl[64], rowa[64];

    uint32_t* Qs = QKs;
    uint32_t* Ks = QKs + 64 * 36;
    float*    Psf = (float*)PsVs;
    uint32_t* Vs = PsVs;

    int b  = blockIdx.y;
    int i0 = blockIdx.x * 64;
    const __nv_bfloat16* Qb = g_q + (size_t)b * N * C;
    const __nv_bfloat16* Kb = g_k + (size_t)b * N * C;
    const uint32_t* Vb32 = (const uint32_t*)(g_v + (size_t)b * C * N);

    int tid  = threadIdx.x;
    int warp = tid >> 5, lane = tid & 31;
    int gr = lane >> 2, t = lane & 3;
    int r0 = 16 * (warp & 3);            // S & O row base
    int cs = 32 * (warp >> 2);           // S col base
    int co = 128 * (warp >> 2);          // O col base

    int smrow = tid >> 2, smseg = tid & 3;   // softmax: 4 adjacent lanes per row

    float acco[16][4];
#pragma unroll
    for (int i = 0; i < 16; i++)
#pragma unroll
        for (int j = 0; j < 4; j++) acco[i][j] = 0.f;

    if (tid < 64) { rowm[tid] = -3.4e38f; rowl[tid] = 0.f; }
    __syncthreads();

    for (int j0 = 0; j0 < N; j0 += 64) {
        // ---------- S = Q K^T  (4 chunks of 64 channels) ----------
        float accs[4][4] = {};
        for (int k0 = 0; k0 < C; k0 += 64) {
            // stage Q,K chunk: 64 rows x 64 bf16 = 8 uint4 per row
            for (int i = tid; i < 512; i += 256) {
                int rr = i >> 3, cc = i & 7;
                ((uint4*)(Qs + rr * 36))[cc] =
                    ((const uint4*)(Qb + (size_t)(i0 + rr) * C + k0))[cc];
                ((uint4*)(Ks + rr * 36))[cc] =
                    ((const uint4*)(Kb + (size_t)(j0 + rr) * C + k0))[cc];
            }
            __syncthreads();
#pragma unroll
            for (int ks = 0; ks < 4; ks++) {       // 4 k16-steps per chunk
                int kb = ks * 8;                    // k-pair base
                uint32_t a[4];
                a[0] = Qs[(r0 + gr) * 36 + kb + t];
                a[1] = Qs[(r0 + gr + 8) * 36 + kb + t];
                a[2] = Qs[(r0 + gr) * 36 + kb + t + 4];
                a[3] = Qs[(r0 + gr + 8) * 36 + kb + t + 4];
#pragma unroll
                for (int nt = 0; nt < 4; nt++) {
                    int nb = cs + nt * 8;
                    uint32_t bb[2];
                    bb[0] = Ks[(nb + gr) * 36 + kb + t];
                    bb[1] = Ks[(nb + gr) * 36 + kb + t + 4];
                    mma_bf16(accs[nt], a, bb);
                }
            }
            __syncthreads();
        }
        // store scaled S tile (fp32) -> Psf
#pragma unroll
        for (int nt = 0; nt < 4; nt++) {
            int col = cs + nt * 8 + 2 * t;
            float2 v0 = make_float2(accs[nt][0] * SCALE, accs[nt][1] * SCALE);
            float2 v1 = make_float2(accs[nt][2] * SCALE, accs[nt][3] * SCALE);
            *(float2*)&Psf[(r0 + gr) * 68 + col]     = v0;
            *(float2*)&Psf[(r0 + gr + 8) * 68 + col] = v1;
        }
        __syncthreads();

        // ---------- fused online softmax; writes packed bf16 P ----------
        {
            float mprev = rowm[smrow];
            float vals[16];
            float mx = mprev;
            const float* sr = Psf + smrow * 68 + smseg * 16;
#pragma unroll
            for (int j = 0; j < 16; j++) {
                vals[j] = sr[j];
                mx = fmaxf(mx, vals[j]);
            }
            mx = fmaxf(mx, __shfl_xor_sync(0xffffffffu, mx, 1));
            mx = fmaxf(mx, __shfl_xor_sync(0xffffffffu, mx, 2));
            float s = 0.f;
#pragma unroll
            for (int j = 0; j < 16; j++) {
                vals[j] = __expf(vals[j] - mx);
                s += vals[j];
            }
            uint32_t* pr = Pp + smrow * 36 + smseg * 8;
#pragma unroll
            for (int p = 0; p < 8; p++) {
                __nv_bfloat162 pv = __floats2bfloat162_rn(vals[2 * p], vals[2 * p + 1]);
                pr[p] = *(uint32_t*)&pv;
            }
            s += __shfl_xor_sync(0xffffffffu, s, 1);
            s += __shfl_xor_sync(0xffffffffu, s, 2);
            if (smseg == 0) {
                float alpha = __expf(mprev - mx);
                rowa[smrow] = alpha;
                rowm[smrow] = mx;
                rowl[smrow] = rowl[smrow] * alpha + s;
            }
        }
        __syncthreads();

        // ---------- O = O*alpha + P V  (2 V-chunks of 32 seq) ----------
        float al0 = rowa[r0 + gr], al1 = rowa[r0 + gr + 8];
#pragma unroll
        for (int nt = 0; nt < 16; nt++) {
            acco[nt][0] *= al0; acco[nt][1] *= al0;
            acco[nt][2] *= al1; acco[nt][3] *= al1;
        }

        for (int vc = 0; vc < 2; vc++) {
            // stage V chunk: 256 chans x 32 seq bf16 = 16 u32 per chan, stride 17
            int sbase = (j0 + 32 * vc) >> 1;        // u32 offset along seq
            for (int i = tid; i < 4096; i += 256) {
                int ch = i >> 4, sp = i & 15;
                Vs[ch * 17 + sp] = Vb32[(size_t)ch * (N / 2) + sbase + sp];
            }
            __syncthreads();
#pragma unroll
            for (int sub = 0; sub < 2; sub++) {     // 2 k16-steps per chunk
                int st = 2 * vc + sub;               // k-pair base = 8*st in Pp
                uint32_t a[4];
                a[0] = Pp[(r0 + gr) * 36 + 8 * st + t];
                a[1] = Pp[(r0 + gr + 8) * 36 + 8 * st + t];
                a[2] = Pp[(r0 + gr) * 36 + 8 * st + t + 4];
                a[3] = Pp[(r0 + gr + 8) * 36 + 8 * st + t + 4];
#pragma unroll
                for (int nt = 0; nt < 16; nt++) {
                    int nb = co + nt * 8;
                    uint32_t bb[2];
                    bb[0] = Vs[(nb + gr) * 17 + 8 * sub + t];
                    bb[1] = Vs[(nb + gr) * 17 + 8 * sub + t + 4];
                    mma_bf16(acco[nt], a, bb);
                }
            }
            __syncthreads();
        }
    }

    // ---------- finalize ----------
    float inv0 = 1.0f / rowl[r0 + gr];
    float inv1 = 1.0f / rowl[r0 + gr + 8];
    float* Ab = g_att + (size_t)b * N * C;
#pragma unroll
    for (int nt = 0; nt < 16; nt++) {
        int col = co + nt * 8 + 2 * t;
        float2 v0 = make_float2(acco[nt][0] * inv0, acco[nt][1] * inv0);
        float2 v1 = make_float2(acco[nt][2] * inv1, acco[nt][3] * inv1);
        *(float2*)&Ab[(size_t)(i0 + r0 + gr) * C + col]     = v0;
        *(float2*)&Ab[(size_t)(i0 + r0 + gr + 8) * C + col] = v1;
    }
}

// ---------------- kernel 5: proj GEMM + bias + residual, tf32 mma ------------
__global__ __launch_bounds__(256) void proj_gemm(const float* __restrict__ W,
                                                 const float* __restrict__ bias,
                                                 const float* __restrict__ x,
                                                 float* __restrict__ out) {
    __shared__ uint32_t Ws[64 * 36];
    __shared__ uint32_t Bs[32 * 68];
    int b  = blockIdx.z;
    int o0 = blockIdx.y * 64;
    int n0 = blockIdx.x * 64;
    const float* Ab = g_att + (size_t)b * N * C;

    int tid  = threadIdx.x;
    int warp = tid >> 5, lane = tid & 31;
    int gr = lane >> 2, t = lane & 3;
    int r0 = 16 * (warp & 3);
    int c0 = 32 * (warp >> 2);

    float acc[4][4] = {};
    for (int k0 = 0; k0 < C; k0 += 32) {
        for (int i = tid; i < 64 * 32; i += 256) {
            int rr = i >> 5, cc = i & 31;
            Ws[rr * 36 + cc] = f2tf32(W[(size_t)(o0 + rr) * C + k0 + cc]);
        }
        for (int i = tid; i < 64 * 32; i += 256) {
            int nn = i >> 5, kk = i & 31;
            Bs[kk * 68 + nn] = f2tf32(Ab[(size_t)(n0 + nn) * C + k0 + kk]);
        }
        __syncthreads();
#pragma unroll
        for (int ks = 0; ks < 4; ks++) {
            int kb = ks * 8;
            uint32_t a[4];
            a[0] = Ws[(r0 + gr) * 36 + kb + t];
            a[1] = Ws[(r0 + gr + 8) * 36 + kb + t];
            a[2] = Ws[(r0 + gr) * 36 + kb + t + 4];
            a[3] = Ws[(r0 + gr + 8) * 36 + kb + t + 4];
#pragma unroll
            for (int nt = 0; nt < 4; nt++) {
                int nb = c0 + nt * 8;
                uint32_t bb[2];
                bb[0] = Bs[(kb + t) * 68 + nb + gr];
                bb[1] = Bs[(kb + t + 4) * 68 + nb + gr];
                mma_tf32(acc[nt], a, bb);
            }
        }
        __syncthreads();
    }
    int o_a = o0 + r0 + gr, o_b = o_a + 8;
    float bv_a = bias[o_a], bv_b = bias[o_b];
#pragma unroll
    for (int nt = 0; nt < 4; nt++) {
        int n = n0 + c0 + nt * 8 + 2 * t;
        size_t ia = ((size_t)b * C + o_a) * N + n;
        size_t ib = ((size_t)b * C + o_b) * N + n;
        float2 xa = *(const float2*)&x[ia];
        float2 xb = *(const float2*)&x[ib];
        float2 oa = make_float2(acc[nt][0] + bv_a + xa.x, acc[nt][1] + bv_a + xa.y);
        float2 ob = make_float2(acc[nt][2] + bv_b + xb.x, acc[nt][3] + bv_b + xb.y);
        *(float2*)&out[ia] = oa;
        *(float2*)&out[ib] = ob;
    }
}

// ---------------- launch ------------------------------------------------------
extern "C" void kernel_launch(void* const* d_in, const int* in_sizes, int n_in,
                              void* d_out, int out_size) {
    const float* x    = (const float*)d_in[0];
    const float* gns  = (const float*)d_in[1];
    const float* gnb  = (const float*)d_in[2];
    const float* qkvw = (const float*)d_in[3];
    const float* qkvb = (const float*)d_in[4];
    const float* pw   = (const float*)d_in[5];
    const float* pb   = (const float*)d_in[6];
    float* out = (float*)d_out;

    gn_stats<<<B * G, 256>>>(x);
    gn_apply<<<(B * C * N / 4) / 256, 256>>>(x, gns, gnb);

    dim3 gq(N / 64, (3 * C) / 64, B);
    qkv_gemm<<<gq, 256>>>(qkvw, qkvb);

    dim3 gf(N / 64, B);
    flash_kernel<<<gf, 256>>>();

    dim3 gp(N / 64, C / 64, B);
    proj_gemm<<<gp, 256>>>(pw, pb, x, out);
}

// round 10
// speedup vs baseline: 5.7364x; 1.1146x over previous
#include <cuda_runtime.h>
#include <cuda_bf16.h>
#include <cstdint>

#define B 8
#define C 256
#define N 4096            // 64*64
#define G 8
#define CG 32             // channels per group
#define EPS 1e-5f
#define SCALE 0.0625f     // 1/sqrt(256)

// ---------------- scratch ----------------------------------------------------
__device__ float         g_xn[(size_t)B * C * N];   // groupnormed x, [b][c][n]
__device__ __nv_bfloat16 g_q[(size_t)B * N * C];    // Q [b][n][c]
__device__ __nv_bfloat16 g_k[(size_t)B * N * C];    // K [b][n][c]
__device__ __nv_bfloat16 g_v[(size_t)B * C * N];    // V [b][c][n]  (transposed)
__device__ float         g_att[(size_t)B * N * C];  // attention out [b][n][c]
__device__ float         g_mean[B * G];
__device__ float         g_rstd[B * G];

// ---------------- mma / ldmatrix helpers --------------------------------------
__device__ __forceinline__ uint32_t f2tf32(float x) {
    uint32_t r;
    asm("cvt.rna.tf32.f32 %0, %1;" : "=r"(r) : "f"(x));
    return r;
}

__device__ __forceinline__ void mma_tf32(float* d, const uint32_t* a, const uint32_t* b) {
    asm volatile(
        "mma.sync.aligned.m16n8k8.row.col.f32.tf32.tf32.f32 "
        "{%0,%1,%2,%3}, {%4,%5,%6,%7}, {%8,%9}, {%0,%1,%2,%3};\n"
        : "+f"(d[0]), "+f"(d[1]), "+f"(d[2]), "+f"(d[3])
        : "r"(a[0]), "r"(a[1]), "r"(a[2]), "r"(a[3]),
          "r"(b[0]), "r"(b[1]));
}

__device__ __forceinline__ void mma_bf16(float* d, const uint32_t* a,
                                         uint32_t b0, uint32_t b1) {
    asm volatile(
        "mma.sync.aligned.m16n8k16.row.col.f32.bf16.bf16.f32 "
        "{%0,%1,%2,%3}, {%4,%5,%6,%7}, {%8,%9}, {%0,%1,%2,%3};\n"
        : "+f"(d[0]), "+f"(d[1]), "+f"(d[2]), "+f"(d[3])
        : "r"(a[0]), "r"(a[1]), "r"(a[2]), "r"(a[3]),
          "r"(b0), "r"(b1));
}

__device__ __forceinline__ void ldsm_x4(uint32_t& r0, uint32_t& r1,
                                        uint32_t& r2, uint32_t& r3, uint32_t addr) {
    asm volatile("ldmatrix.sync.aligned.m8n8.x4.shared.b16 {%0,%1,%2,%3}, [%4];"
                 : "=r"(r0), "=r"(r1), "=r"(r2), "=r"(r3) : "r"(addr));
}

__device__ __forceinline__ uint32_t smem_u32(const void* p) {
    return (uint32_t)__cvta_generic_to_shared(p);
}

// ---------------- kernel 1: groupnorm stats ----------------------------------
__global__ void gn_stats(const float* __restrict__ x) {
    int bg = blockIdx.x;
    const float4* p = (const float4*)(x + (size_t)bg * CG * N);
    float s = 0.f, ss = 0.f;
    for (int i = threadIdx.x; i < (CG * N) / 4; i += blockDim.x) {
        float4 v = p[i];
        s  += v.x + v.y + v.z + v.w;
        ss += v.x * v.x + v.y * v.y + v.z * v.z + v.w * v.w;
    }
    for (int o = 16; o > 0; o >>= 1) {
        s  += __shfl_down_sync(0xffffffffu, s, o);
        ss += __shfl_down_sync(0xffffffffu, ss, o);
    }
    __shared__ float rs[8], rss[8];
    int wid = threadIdx.x >> 5, lid = threadIdx.x & 31;
    if (lid == 0) { rs[wid] = s; rss[wid] = ss; }
    __syncthreads();
    if (threadIdx.x == 0) {
        float ts = 0.f, tss = 0.f;
        for (int i = 0; i < 8; i++) { ts += rs[i]; tss += rss[i]; }
        float inv = 1.0f / (float)(CG * N);
        float mean = ts * inv;
        float var = tss * inv - mean * mean;
        g_mean[bg] = mean;
        g_rstd[bg] = rsqrtf(var + EPS);
    }
}

// ---------------- kernel 2: groupnorm apply ----------------------------------
__global__ void gn_apply(const float* __restrict__ x,
                         const float* __restrict__ sc,
                         const float* __restrict__ bi) {
    int i = blockIdx.x * blockDim.x + threadIdx.x;
    int e = i << 2;
    int c = (e >> 12) & (C - 1);
    int bg = e >> 17;
    float m = g_mean[bg], r = g_rstd[bg];
    float a = sc[c] * r;
    float b = bi[c] - m * a;
    float4 v = ((const float4*)x)[i];
    float4 o;
    o.x = v.x * a + b; o.y = v.y * a + b; o.z = v.z * a + b; o.w = v.w * a + b;
    ((float4*)g_xn)[i] = o;
}

// ---------------- kernel 3: QKV GEMM, tf32 mma; writes bf16 ------------------
__global__ __launch_bounds__(256) void qkv_gemm(const float* __restrict__ W,
                                                const float* __restrict__ bias) {
    __shared__ uint32_t Ws[64 * 36];
    __shared__ uint32_t Xs[32 * 72];
    int b  = blockIdx.z;
    int o0 = blockIdx.y * 64;
    int n0 = blockIdx.x * 64;
    const float* Xb = g_xn + (size_t)b * C * N;

    int tid  = threadIdx.x;
    int warp = tid >> 5, lane = tid & 31;
    int gr = lane >> 2, t = lane & 3;
    int r0 = 16 * (warp & 3);
    int c0 = 32 * (warp >> 2);

    float acc[4][4] = {};
    for (int k0 = 0; k0 < C; k0 += 32) {
        for (int i = tid; i < 64 * 32; i += 256) {
            int rr = i >> 5, cc = i & 31;
            Ws[rr * 36 + cc] = f2tf32(W[(size_t)(o0 + rr) * C + k0 + cc]);
        }
        for (int i = tid; i < 32 * 64; i += 256) {
            int kk = i >> 6, nn = i & 63;
            Xs[kk * 72 + nn] = f2tf32(Xb[(size_t)(k0 + kk) * N + n0 + nn]);
        }
        __syncthreads();
#pragma unroll
        for (int ks = 0; ks < 4; ks++) {
            int kb = ks * 8;
            uint32_t a[4];
            a[0] = Ws[(r0 + gr) * 36 + kb + t];
            a[1] = Ws[(r0 + gr + 8) * 36 + kb + t];
            a[2] = Ws[(r0 + gr) * 36 + kb + t + 4];
            a[3] = Ws[(r0 + gr + 8) * 36 + kb + t + 4];
#pragma unroll
            for (int nt = 0; nt < 4; nt++) {
                int nb = c0 + nt * 8;
                uint32_t bb[2];
                bb[0] = Xs[(kb + t) * 72 + nb + gr];
                bb[1] = Xs[(kb + t + 4) * 72 + nb + gr];
                mma_tf32(acc[nt], a, bb);
            }
        }
        __syncthreads();
    }
    int o_a = o0 + r0 + gr, o_b = o_a + 8;
    float bv_a = bias[o_a], bv_b = bias[o_b];
    if (o0 < 512) {
        __nv_bfloat16* dst = (o0 < 256) ? g_q : g_k;
        int oc_a = o_a & 255, oc_b = o_b & 255;
#pragma unroll
        for (int nt = 0; nt < 4; nt++) {
            int n = n0 + c0 + nt * 8 + 2 * t;
            dst[((size_t)b * N + n)     * C + oc_a] = __float2bfloat16(acc[nt][0] + bv_a);
            dst[((size_t)b * N + n + 1) * C + oc_a] = __float2bfloat16(acc[nt][1] + bv_a);
            dst[((size_t)b * N + n)     * C + oc_b] = __float2bfloat16(acc[nt][2] + bv_b);
            dst[((size_t)b * N + n + 1) * C + oc_b] = __float2bfloat16(acc[nt][3] + bv_b);
        }
    } else {
        int oc_a = o_a - 512, oc_b = o_b - 512;
#pragma unroll
        for (int nt = 0; nt < 4; nt++) {
            int n = n0 + c0 + nt * 8 + 2 * t;
            __nv_bfloat162 va = __floats2bfloat162_rn(acc[nt][0] + bv_a, acc[nt][1] + bv_a);
            __nv_bfloat162 vb = __floats2bfloat162_rn(acc[nt][2] + bv_b, acc[nt][3] + bv_b);
            *(__nv_bfloat162*)&g_v[((size_t)b * C + oc_a) * N + n] = va;
            *(__nv_bfloat162*)&g_v[((size_t)b * C + oc_b) * N + n] = vb;
        }
    }
}

// ---------------- kernel 4: flash attention, bf16 mma + ldmatrix --------------
// Br = Bc = 64, 256 threads (8 warps).
// Smem (48,896 B):
//   QKs[2*64*36] u32 : Q,K chunk (64 rows x 64 bf16, stride 36)
//   PsVs[5120] u32   : S fp32 [64][68]  ALIAS  V stage [256 ch][20] (16 u32 data)
//   Pp[64*36] u32    : packed bf16 P (stride 36)
__global__ __launch_bounds__(256) void flash_kernel() {
    __shared__ __align__(16) uint32_t QKs[2 * 64 * 36];
    __shared__ __align__(16) uint32_t PsVs[5120];
    __shared__ __align__(16) uint32_t Pp[64 * 36];
    __shared__ float rowm[64], rowl[64], rowa[64];

    uint32_t* Qs = QKs;
    uint32_t* Ks = QKs + 64 * 36;
    float*    Psf = (float*)PsVs;
    uint32_t* Vs = PsVs;

    int b  = blockIdx.y;
    int i0 = blockIdx.x * 64;
    const __nv_bfloat16* Qb = g_q + (size_t)b * N * C;
    const __nv_bfloat16* Kb = g_k + (size_t)b * N * C;
    const uint32_t* Vb32 = (const uint32_t*)(g_v + (size_t)b * C * N);

    int tid  = threadIdx.x;
    int warp = tid >> 5, lane = tid & 31;
    int gr = lane >> 2, t = lane & 3;
    int r0 = 16 * (warp & 3);            // S & O row base
    int cs = 32 * (warp >> 2);           // S col base
    int co = 128 * (warp >> 2);          // O col base

    int smrow = tid >> 2, smseg = tid & 3;

    // ldmatrix lane-address precompute
    int l15 = lane & 15, l7 = lane & 7;
    int hi16 = lane >> 4;                // 0/1: col-half for A, row-half for B
    int bsel = (lane >> 3) & 1;          // 0/1: col-half for B
    uint32_t qa_addr = smem_u32(Qs) + 4u * ((r0 + l15) * 36 + 4 * hi16);
    uint32_t pa_addr = smem_u32(Pp) + 4u * ((r0 + l15) * 36 + 4 * hi16);
    uint32_t kb_addr = smem_u32(Ks) + 4u * ((cs + l7 + 8 * hi16) * 36 + 4 * bsel);
    uint32_t vb_addr = smem_u32(Vs) + 4u * ((co + l7 + 8 * hi16) * 20 + 4 * bsel);

    float acco[16][4];
#pragma unroll
    for (int i = 0; i < 16; i++)
#pragma unroll
        for (int j = 0; j < 4; j++) acco[i][j] = 0.f;

    if (tid < 64) { rowm[tid] = -3.4e38f; rowl[tid] = 0.f; }
    __syncthreads();

    for (int j0 = 0; j0 < N; j0 += 64) {
        // ---------- S = Q K^T (4 chunks of 64 channels) ----------
        float accs[4][4] = {};
        for (int k0 = 0; k0 < C; k0 += 64) {
            for (int i = tid; i < 512; i += 256) {
                int rr = i >> 3, cc = i & 7;
                ((uint4*)(Qs + rr * 36))[cc] =
                    ((const uint4*)(Qb + (size_t)(i0 + rr) * C + k0))[cc];
                ((uint4*)(Ks + rr * 36))[cc] =
                    ((const uint4*)(Kb + (size_t)(j0 + rr) * C + k0))[cc];
            }
            __syncthreads();
#pragma unroll
            for (int ks = 0; ks < 4; ks++) {
                uint32_t a[4];
                ldsm_x4(a[0], a[1], a[2], a[3], qa_addr + 32 * ks);
                uint32_t b0, b1, b2, b3, b4, b5, b6, b7;
                ldsm_x4(b0, b1, b2, b3, kb_addr + 32 * ks);          // nt 0,1
                ldsm_x4(b4, b5, b6, b7, kb_addr + 2304 + 32 * ks);   // nt 2,3
                mma_bf16(accs[0], a, b0, b1);
                mma_bf16(accs[1], a, b2, b3);
                mma_bf16(accs[2], a, b4, b5);
                mma_bf16(accs[3], a, b6, b7);
            }
            __syncthreads();
        }
        // store scaled S tile (fp32) -> Psf
#pragma unroll
        for (int nt = 0; nt < 4; nt++) {
            int col = cs + nt * 8 + 2 * t;
            float2 v0 = make_float2(accs[nt][0] * SCALE, accs[nt][1] * SCALE);
            float2 v1 = make_float2(accs[nt][2] * SCALE, accs[nt][3] * SCALE);
            *(float2*)&Psf[(r0 + gr) * 68 + col]     = v0;
            *(float2*)&Psf[(r0 + gr + 8) * 68 + col] = v1;
        }
        __syncthreads();

        // ---------- fused online softmax; writes packed bf16 P ----------
        {
            float mprev = rowm[smrow];
            float vals[16];
            float mx = mprev;
            const float* sr = Psf + smrow * 68 + smseg * 16;
#pragma unroll
            for (int j = 0; j < 16; j++) {
                vals[j] = sr[j];
                mx = fmaxf(mx, vals[j]);
            }
            mx = fmaxf(mx, __shfl_xor_sync(0xffffffffu, mx, 1));
            mx = fmaxf(mx, __shfl_xor_sync(0xffffffffu, mx, 2));
            float s = 0.f;
#pragma unroll
            for (int j = 0; j < 16; j++) {
                vals[j] = __expf(vals[j] - mx);
                s += vals[j];
            }
            uint32_t* pr = Pp + smrow * 36 + smseg * 8;
#pragma unroll
            for (int p = 0; p < 8; p++) {
                __nv_bfloat162 pv = __floats2bfloat162_rn(vals[2 * p], vals[2 * p + 1]);
                pr[p] = *(uint32_t*)&pv;
            }
            s += __shfl_xor_sync(0xffffffffu, s, 1);
            s += __shfl_xor_sync(0xffffffffu, s, 2);
            if (smseg == 0) {
                float alpha = __expf(mprev - mx);
                rowa[smrow] = alpha;
                rowm[smrow] = mx;
                rowl[smrow] = rowl[smrow] * alpha + s;
            }
        }
        __syncthreads();

        // ---------- O = O*alpha + P V (2 V-chunks of 32 seq) ----------
        float al0 = rowa[r0 + gr], al1 = rowa[r0 + gr + 8];
#pragma unroll
        for (int nt = 0; nt < 16; nt++) {
            acco[nt][0] *= al0; acco[nt][1] *= al0;
            acco[nt][2] *= al1; acco[nt][3] *= al1;
        }

        for (int vc = 0; vc < 2; vc++) {
            // stage V chunk: 256 chans x 32 seq bf16 = 16 u32/row, stride 20, uint4
            int sbase = (j0 + 32 * vc) >> 1;
            for (int i = tid; i < 1024; i += 256) {
                int ch = i >> 2, q = (i & 3) << 2;
                *(uint4*)(Vs + ch * 20 + q) =
                    *(const uint4*)(Vb32 + (size_t)ch * (N / 2) + sbase + q);
            }
            __syncthreads();
#pragma unroll
            for (int sub = 0; sub < 2; sub++) {
                int st = 2 * vc + sub;
                uint32_t a[4];
                ldsm_x4(a[0], a[1], a[2], a[3], pa_addr + 32 * st);
#pragma unroll
                for (int ntp = 0; ntp < 8; ntp++) {
                    uint32_t v0, v1, v2, v3;
                    ldsm_x4(v0, v1, v2, v3, vb_addr + 1280 * ntp + 32 * sub);
                    mma_bf16(acco[2 * ntp],     a, v0, v1);
                    mma_bf16(acco[2 * ntp + 1], a, v2, v3);
                }
            }
            __syncthreads();
        }
    }

    // ---------- finalize ----------
    float inv0 = 1.0f / rowl[r0 + gr];
    float inv1 = 1.0f / rowl[r0 + gr + 8];
    float* Ab = g_att + (size_t)b * N * C;
#pragma unroll
    for (int nt = 0; nt < 16; nt++) {
        int col = co + nt * 8 + 2 * t;
        float2 v0 = make_float2(acco[nt][0] * inv0, acco[nt][1] * inv0);
        float2 v1 = make_float2(acco[nt][2] * inv1, acco[nt][3] * inv1);
        *(float2*)&Ab[(size_t)(i0 + r0 + gr) * C + col]     = v0;
        *(float2*)&Ab[(size_t)(i0 + r0 + gr + 8) * C + col] = v1;
    }
}

// ---------------- kernel 5: proj GEMM + bias + residual, tf32 mma ------------
__global__ __launch_bounds__(256) void proj_gemm(const float* __restrict__ W,
                                                 const float* __restrict__ bias,
                                                 const float* __restrict__ x,
                                                 float* __restrict__ out) {
    __shared__ uint32_t Ws[64 * 36];
    __shared__ uint32_t Bs[32 * 68];
    int b  = blockIdx.z;
    int o0 = blockIdx.y * 64;
    int n0 = blockIdx.x * 64;
    const float* Ab = g_att + (size_t)b * N * C;

    int tid  = threadIdx.x;
    int warp = tid >> 5, lane = tid & 31;
    int gr = lane >> 2, t = lane & 3;
    int r0 = 16 * (warp & 3);
    int c0 = 32 * (warp >> 2);

    float acc[4][4] = {};
    for (int k0 = 0; k0 < C; k0 += 32) {
        for (int i = tid; i < 64 * 32; i += 256) {
            int rr = i >> 5, cc = i & 31;
            Ws[rr * 36 + cc] = f2tf32(W[(size_t)(o0 + rr) * C + k0 + cc]);
        }
        for (int i = tid; i < 64 * 32; i += 256) {
            int nn = i >> 5, kk = i & 31;
            Bs[kk * 68 + nn] = f2tf32(Ab[(size_t)(n0 + nn) * C + k0 + kk]);
        }
        __syncthreads();
#pragma unroll
        for (int ks = 0; ks < 4; ks++) {
            int kb = ks * 8;
            uint32_t a[4];
            a[0] = Ws[(r0 + gr) * 36 + kb + t];
            a[1] = Ws[(r0 + gr + 8) * 36 + kb + t];
            a[2] = Ws[(r0 + gr) * 36 + kb + t + 4];
            a[3] = Ws[(r0 + gr + 8) * 36 + kb + t + 4];
#pragma unroll
            for (int nt = 0; nt < 4; nt++) {
                int nb = c0 + nt * 8;
                uint32_t bb[2];
                bb[0] = Bs[(kb + t) * 68 + nb + gr];
                bb[1] = Bs[(kb + t + 4) * 68 + nb + gr];
                mma_tf32(acc[nt], a, bb);
            }
        }
        __syncthreads();
    }
    int o_a = o0 + r0 + gr, o_b = o_a + 8;
    float bv_a = bias[o_a], bv_b = bias[o_b];
#pragma unroll
    for (int nt = 0; nt < 4; nt++) {
        int n = n0 + c0 + nt * 8 + 2 * t;
        size_t ia = ((size_t)b * C + o_a) * N + n;
        size_t ib = ((size_t)b * C + o_b) * N + n;
        float2 xa = *(const float2*)&x[ia];
        float2 xb = *(const float2*)&x[ib];
        float2 oa = make_float2(acc[nt][0] + bv_a + xa.x, acc[nt][1] + bv_a + xa.y);
        float2 ob = make_float2(acc[nt][2] + bv_b + xb.x, acc[nt][3] + bv_b + xb.y);
        *(float2*)&out[ia] = oa;
        *(float2*)&out[ib] = ob;
    }
}

// ---------------- launch ------------------------------------------------------
extern "C" void kernel_launch(void* const* d_in, const int* in_sizes, int n_in,
                              void* d_out, int out_size) {
    const float* x    = (const float*)d_in[0];
    const float* gns  = (const float*)d_in[1];
    const float* gnb  = (const float*)d_in[2];
    const float* qkvw = (const float*)d_in[3];
    const float* qkvb = (const float*)d_in[4];
    const float* pw   = (const float*)d_in[5];
    const float* pb   = (const float*)d_in[6];
    float* out = (float*)d_out;

    gn_stats<<<B * G, 256>>>(x);
    gn_apply<<<(B * C * N / 4) / 256, 256>>>(x, gns, gnb);

    dim3 gq(N / 64, (3 * C) / 64, B);
    qkv_gemm<<<gq, 256>>>(qkvw, qkvb);

    dim3 gf(N / 64, B);
    flash_kernel<<<gf, 256>>>();

    dim3 gp(N / 64, C / 64, B);
    proj_gemm<<<gp, 256>>>(pw, pb, x, out);
}